// round 11
// baseline (speedup 1.0000x reference)
#include <cuda_runtime.h>
#include <cuda_bf16.h>
#include <cstdint>
#include <cstddef>

#define B_ 8192
#define T_ 21
#define M_ (B_*T_)          /* 172032 = 2688*64 */
#define NTILE 2688          /* 64-row tiles */
#define NSTAGES 64          /* 16 (L1) + 32 (L2) + 16 (L3) weight stages of 12KB */

/* smem byte offsets (per CTA: ~108.3KB, 2 CTAs/SM) */
#define SO_A0    0u         /* 32KB: x (L1 in), then h2 (L3 in) */
#define SO_A1    32768u     /* 32KB: h1 (L2 in) */
#define SO_W     65536u     /* 3 x 12KB weight stage ring */
#define SO_BIAS  102400u    /* 1920 floats */
#define SO_FCW   110080u    /* 128 floats */
#define SO_RED   110592u    /* 64 floats */
#define SMEM_TOT 110848

/* ---- device scratch (allocation-free rule: __device__ globals) ---- */
__device__ __align__(128) unsigned char g_xA[(size_t)NTILE*16384];   /* per-tile swizzled bf16 x images */
__device__ __align__(128) unsigned char g_Wimg[NSTAGES*12288];       /* pre-swizzled weight stages */
__device__ float g_bias[1920];   /* [L1 i|g|o 768, L2 768, L3 384] */
__device__ float g_y[M_];

/* ---- helpers ---- */
__device__ __forceinline__ uint32_t s2u(const void* p){ return (uint32_t)__cvta_generic_to_shared(p); }
__device__ __forceinline__ void cpa16(void* dst, const void* src){
    asm volatile("cp.async.ca.shared.global [%0], [%1], 16;" :: "r"(s2u(dst)), "l"(src));
}
__device__ __forceinline__ void cp_commit(){ asm volatile("cp.async.commit_group;"); }
template<int N> __device__ __forceinline__ void cp_wait(){ asm volatile("cp.async.wait_group %0;" :: "n"(N)); }

__device__ __forceinline__ void ldsm4(uint32_t* r, const void* p){
    asm volatile("ldmatrix.sync.aligned.m8n8.x4.shared.b16 {%0,%1,%2,%3}, [%4];"
        : "=r"(r[0]),"=r"(r[1]),"=r"(r[2]),"=r"(r[3]) : "r"(s2u(p)));
}
__device__ __forceinline__ void mma16816(float* c, const uint32_t* a, uint32_t b0, uint32_t b1){
    asm volatile("mma.sync.aligned.m16n8k16.row.col.f32.bf16.bf16.f32 "
        "{%0,%1,%2,%3},{%4,%5,%6,%7},{%8,%9},{%0,%1,%2,%3};"
        : "+f"(c[0]),"+f"(c[1]),"+f"(c[2]),"+f"(c[3])
        : "r"(a[0]),"r"(a[1]),"r"(a[2]),"r"(a[3]),"r"(b0),"r"(b1));
}
__device__ __forceinline__ uint32_t pk2(float lo, float hi){
    uint32_t r; asm("cvt.rn.bf16x2.f32 %0, %1, %2;" : "=r"(r) : "f"(hi), "f"(lo)); return r;
}
/* fast activations: 4 MUFU per hval */
__device__ __forceinline__ float tanhap(float x){
    float y; asm("tanh.approx.f32 %0, %1;" : "=f"(y) : "f"(x)); return y;
}
__device__ __forceinline__ float sigap(float x){ return fmaf(tanhap(0.5f*x), 0.5f, 0.5f); }
__device__ __forceinline__ float hval(float iv, float gv, float ov){
    float cv = sigap(iv) * tanhap(gv);
    return sigap(ov) * tanhap(cv);
}

/* ---- prep: weights -> pre-swizzled 12KB stages in consumption order ---- */
__global__ void pack_kernel(const float* __restrict__ W1,const float* __restrict__ b1i,const float* __restrict__ b1h,
                            const float* __restrict__ W2,const float* __restrict__ b2i,const float* __restrict__ b2h,
                            const float* __restrict__ W3,const float* __restrict__ b3i,const float* __restrict__ b3h){
    int idx = blockIdx.x*256 + threadIdx.x;
    if (idx < NSTAGES*6144){
        int ss = idx / 6144, e = idx % 6144;
        int nrow = e >> 6, kk = e & 63;
        int l, jc, kc;
        if (ss < 16){ l = 0; jc = ss >> 1; kc = ss & 1; }
        else if (ss < 48){ int s = ss-16; l = 1; jc = s >> 2; kc = s & 3; }
        else { int s = ss-48; l = 2; jc = s >> 2; kc = s & 3; }
        int g = nrow >> 5, n = nrow & 31;
        int H = (l<2) ? 256 : 128;
        int K = (l==0) ? 128 : 256;
        int j = jc*32 + n;
        int row = (g==0) ? j : (g==1) ? 2*H+j : 3*H+j;   /* gates i,g,o from i,f,g,o */
        const float* W = (l==0) ? W1 : (l==1) ? W2 : W3;
        float v = W[(size_t)row*K + kc*64 + kk];
        uint32_t off = (uint32_t)nrow*128u + ((((uint32_t)(kk>>3)) ^ (nrow&7))<<4) + ((2u*kk)&15);
        *reinterpret_cast<__nv_bfloat16*>(g_Wimg + (size_t)ss*12288 + off) = __float2bfloat16_rn(v);
        return;
    }
    idx -= NSTAGES*6144;
    if (idx < 1920){
        int l = (idx<768)?0:(idx<1536)?1:2;
        int base = (l==0)?0:(l==1)?768:1536;
        int H = (l<2)?256:128;
        int q = idx - base, g = q / H, j = q % H;
        int row = (g==0)? j : (g==1)? 2*H+j : 3*H+j;
        const float* bi = (l==0)?b1i:(l==1)?b2i:b3i;
        const float* bh = (l==0)?b1h:(l==1)?b2h:b3h;
        g_bias[idx] = bi[row] + bh[row];
    }
}

/* ---- prep: x (B,128,21) -> per-64-row-tile swizzled bf16 A images (row 256B) ---- */
__global__ void transpose_kernel(const float* __restrict__ x){
    __shared__ float sx[2688];
    int b = blockIdx.x, tid = threadIdx.x;   /* 256 threads */
    const float* xb = x + (size_t)b*2688;
    for (int i = tid; i < 2688; i += 256) sx[i] = xb[i];
    __syncthreads();
    for (int i = tid; i < 1344; i += 256){
        int t = i >> 6, kp = (i & 63) * 2;
        int m = b*21 + t, tt = m >> 6, r = m & 63;
        uint32_t v = pk2(sx[kp*21 + t], sx[(kp+1)*21 + t]);
        uint32_t off = (uint32_t)r*256u + ((((uint32_t)(kp>>3)) ^ (r&7))<<4) + ((2u*kp)&15);
        *reinterpret_cast<uint32_t*>(g_xA + (size_t)tt*16384 + off) = v;
    }
}

/* ---- weight stage fill: pure linear copy into ring slot (image pre-swizzled) ---- */
__device__ __forceinline__ void fill_stage(char* smem, int stage, int slot, int tid){
    char* dst = smem + SO_W + (uint32_t)slot*12288u;
    const unsigned char* src = g_Wimg + (size_t)stage*12288;
    #pragma unroll
    for (int it = 0; it < 6; ++it){
        int ch = tid + it*128;
        cpa16(dst + ch*16, src + ch*16);
    }
}

/* ---- epilogue for one h-pair q (0..7) of column-chunk pjc ---- */
template<int H, int LAST>
__device__ __forceinline__ void epi_pair(float (&accP)[3][2][2][4], int q, int pjc,
                                         char* Aout, const float* fcw, float* yp,
                                         int lane, int mw, int nw){
    const int nf = q >> 2, mf = (q >> 1) & 1, hf = q & 1;
    const int j0 = pjc*32 + nw*16 + nf*8 + 2*(lane & 3);
    const float h0 = hval(accP[0][mf][nf][2*hf],   accP[1][mf][nf][2*hf],   accP[2][mf][nf][2*hf]);
    const float h1 = hval(accP[0][mf][nf][2*hf+1], accP[1][mf][nf][2*hf+1], accP[2][mf][nf][2*hf+1]);
    if (!LAST){
        const uint32_t row = 32*mw + 16*mf + 8*hf + (lane>>2);
        const uint32_t b = 2u*(uint32_t)j0;
        const uint32_t off = row*(2u*H) + ((((b>>4) ^ (row&7)))<<4) + (b&15);
        *reinterpret_cast<uint32_t*>(Aout + off) = pk2(h0, h1);
    } else {
        yp[mf*2+hf] = fmaf(h0, fcw[j0], fmaf(h1, fcw[j0+1], yp[mf*2+hf]));
    }
}

/* ---- one jc pass: accumulate column-chunk jc into acc; if DEF, drain accP (jc=pjc) ---- */
template<int K, int H, int LAST, int DEF>
__device__ __forceinline__ void kc_pass(char* smem, const char* Ain, char* Aout,
                                        float (&acc)[3][2][2][4], float (&accP)[3][2][2][4],
                                        int jc, int pjc, int& ss, int& rslot,
                                        const float* biasL, const float* fcw, float* yp, int tid){
    const int wid = tid >> 5, lane = tid & 31;
    const int mw = wid >> 1, nw = wid & 1;
    const uint32_t arow = 32*mw + (lane & 15);
    const uint32_t ax = arow & 7;
    const uint32_t nrow = nw*16 + 8*(lane>>4) + (lane & 7);
    const uint32_t bx = nrow & 7;
    constexpr int NK = K/64;
    constexpr int CH = 8/NK;       /* h-pairs drained per kc */

    /* bias-folded accumulator init */
    {
        const int j0b = jc*32 + nw*16 + 2*(lane & 3);
        #pragma unroll
        for (int g = 0; g < 3; ++g){
            #pragma unroll
            for (int nf = 0; nf < 2; ++nf){
                const float b0v = biasL[g*H + j0b + nf*8];
                const float b1v = biasL[g*H + j0b + nf*8 + 1];
                #pragma unroll
                for (int mf = 0; mf < 2; ++mf){
                    #pragma unroll
                    for (int hf = 0; hf < 2; ++hf){
                        acc[g][mf][nf][2*hf]   = b0v;
                        acc[g][mf][nf][2*hf+1] = b1v;
                    }
                }
            }
        }
    }

    #pragma unroll
    for (int kc = 0; kc < NK; ++kc){
        cp_wait<1>();
        __syncthreads();               /* stage ss visible to all */
        const char* ws = smem + SO_W + (uint32_t)rslot*12288u;
        #pragma unroll
        for (int ks = 0; ks < 4; ++ks){
            const uint32_t cA = (uint32_t)(kc*8 + 2*ks) + (lane>>4);
            const uint32_t aoff = arow*(2u*K) + (((cA ^ ax))<<4);
            uint32_t a0[4], a1[4];
            ldsm4(a0, Ain + aoff);
            ldsm4(a1, Ain + aoff + 32u*K);
            const uint32_t cb = (uint32_t)(2*ks) + ((lane>>3)&1);
            const uint32_t boff = nrow*128u + (((cb ^ bx))<<4);
            uint32_t b0[4], b1[4], b2[4];
            ldsm4(b0, ws + boff);
            ldsm4(b1, ws + boff + 4096);
            ldsm4(b2, ws + boff + 8192);
            mma16816(acc[0][0][0], a0, b0[0], b0[1]);
            mma16816(acc[0][0][1], a0, b0[2], b0[3]);
            mma16816(acc[0][1][0], a1, b0[0], b0[1]);
            mma16816(acc[0][1][1], a1, b0[2], b0[3]);
            mma16816(acc[1][0][0], a0, b1[0], b1[1]);
            mma16816(acc[1][0][1], a0, b1[2], b1[3]);
            mma16816(acc[1][1][0], a1, b1[0], b1[1]);
            mma16816(acc[1][1][1], a1, b1[2], b1[3]);
            mma16816(acc[2][0][0], a0, b2[0], b2[1]);
            mma16816(acc[2][0][1], a0, b2[2], b2[3]);
            mma16816(acc[2][1][0], a1, b2[0], b2[1]);
            mma16816(acc[2][1][1], a1, b2[2], b2[3]);
        }
        if (ss + 2 < NSTAGES){
            int wslot = rslot + 2; if (wslot >= 3) wslot -= 3;
            fill_stage(smem, ss + 2, wslot, tid);
        }
        cp_commit();                   /* exactly one commit per kc */
        ++ss;
        ++rslot; if (rslot == 3) rslot = 0;
        if (DEF){                      /* drain previous jc in the tensor shadow */
            #pragma unroll
            for (int u = 0; u < CH; ++u)
                epi_pair<H,LAST>(accP, kc*CH + u, pjc, Aout, fcw, yp, lane, mw, nw);
        }
    }
}

/* ---- one fused layer with cross-jc software pipelining ---- */
template<int K, int H, int LAST>
__device__ __forceinline__ void run_layer(char* smem, const char* Ain, char* Aout,
                                          int& ss, int& rslot, const float* biasL, const float* fcw,
                                          float* yp, int tid){
    constexpr int NJ = H/32;           /* even: 8 or 4 */
    const int wid = tid >> 5, lane = tid & 31;
    const int mw = wid >> 1, nw = wid & 1;
    float accA[3][2][2][4], accB[3][2][2][4];

    kc_pass<K,H,LAST,0>(smem, Ain, Aout, accA, accB, 0, 0, ss, rslot, biasL, fcw, yp, tid);
    #pragma unroll 1
    for (int jcp = 0; jcp + 1 < NJ; jcp += 2){
        kc_pass<K,H,LAST,1>(smem, Ain, Aout, accB, accA, jcp+1, jcp,   ss, rslot, biasL, fcw, yp, tid);
        if (jcp + 2 < NJ)
            kc_pass<K,H,LAST,1>(smem, Ain, Aout, accA, accB, jcp+2, jcp+1, ss, rslot, biasL, fcw, yp, tid);
    }
    /* final serial drain: jc = NJ-1 lives in accB (NJ even) */
    #pragma unroll
    for (int q = 0; q < 8; ++q)
        epi_pair<H,LAST>(accB, q, NJ-1, Aout, fcw, yp, lane, mw, nw);
}

/* ---- fused main kernel: 3 LSTM layers + fc1; 64-row tiles, 2 CTAs/SM ---- */
__global__ void __launch_bounds__(128,2)
lstm_main(const float* __restrict__ fc1w, const float* __restrict__ fc1b){
    extern __shared__ char smem[];
    char* A0 = smem + SO_A0;
    char* A1 = smem + SO_A1;
    float* biasS = (float*)(smem + SO_BIAS);
    float* fcw   = (float*)(smem + SO_FCW);
    float* red   = (float*)(smem + SO_RED);
    const int tid = threadIdx.x, lane = tid & 31, wid = tid >> 5;
    const int mw = wid >> 1, nw = wid & 1;
    const float fc1b0 = __ldg(fc1b);

    /* x tile (64 x 128 bf16, 16KB) -> A0 */
    #pragma unroll
    for (int it = 0; it < 8; ++it){
        int ch = tid + it*128;
        cpa16(A0 + ch*16, g_xA + (size_t)blockIdx.x*16384 + ch*16);
    }
    cp_commit();
    fill_stage(smem, 0, 0, tid); cp_commit();
    fill_stage(smem, 1, 1, tid); cp_commit();

    for (int i = tid; i < 1920; i += 128) biasS[i] = g_bias[i];
    if (tid < 128) fcw[tid] = fc1w[tid];

    int ss = 0, rslot = 0;
    float yp[4] = {0.f, 0.f, 0.f, 0.f};
    run_layer<128,256,0>(smem, A0, A1, ss, rslot, biasS,        fcw, yp, tid);
    run_layer<256,256,0>(smem, A1, A0, ss, rslot, biasS + 768,  fcw, yp, tid);
    run_layer<256,128,1>(smem, A0, A1, ss, rslot, biasS + 1536, fcw, yp, tid);

    /* fc1 reduce: sum across quad lanes, then across nw halves */
    #pragma unroll
    for (int k = 0; k < 4; ++k){
        yp[k] += __shfl_xor_sync(0xffffffffu, yp[k], 1);
        yp[k] += __shfl_xor_sync(0xffffffffu, yp[k], 2);
    }
    __syncthreads();
    if (nw == 0 && (lane & 3) == 0){
        #pragma unroll
        for (int k = 0; k < 4; ++k){
            int row = 32*mw + 16*(k>>1) + 8*(k&1) + (lane>>2);
            red[row] = yp[k];
        }
    }
    __syncthreads();
    if (nw == 1 && (lane & 3) == 0){
        #pragma unroll
        for (int k = 0; k < 4; ++k){
            int row = 32*mw + 16*(k>>1) + 8*(k&1) + (lane>>2);
            g_y[(size_t)blockIdx.x*64 + row] = red[row] + yp[k] + fc1b0;
        }
    }
}

/* ---- fc2: out[b,0,t] = sum_j y[b,j]*w[t,j] + bias[t] ---- */
__global__ void fc2_kernel(const float* __restrict__ w, const float* __restrict__ bias,
                           float* __restrict__ out){
    __shared__ float sw[T_*T_];
    __shared__ float sbv[T_];
    int tid = threadIdx.x;
    for (int i = tid; i < T_*T_; i += 256) sw[i] = w[i];
    if (tid < T_) sbv[tid] = bias[tid];
    __syncthreads();
    int gidx = blockIdx.x*256 + tid;
    int b = gidx / T_, t = gidx - b*T_;
    const float* yb = g_y + (size_t)b*T_;
    float s = sbv[t];
    #pragma unroll
    for (int j = 0; j < T_; ++j) s += yb[j]*sw[t*T_ + j];
    out[gidx] = s;
}

/* ---- launch ---- */
extern "C" void kernel_launch(void* const* d_in, const int* in_sizes, int n_in,
                              void* d_out, int out_size){
    const float* x   = (const float*)d_in[0];
    const float* W1  = (const float*)d_in[1];
    const float* b1i = (const float*)d_in[2];
    const float* b1h = (const float*)d_in[3];
    const float* W2  = (const float*)d_in[4];
    const float* b2i = (const float*)d_in[5];
    const float* b2h = (const float*)d_in[6];
    const float* W3  = (const float*)d_in[7];
    const float* b3i = (const float*)d_in[8];
    const float* b3h = (const float*)d_in[9];
    const float* f1w = (const float*)d_in[10];
    const float* f1b = (const float*)d_in[11];
    const float* f2w = (const float*)d_in[12];
    const float* f2b = (const float*)d_in[13];
    float* out = (float*)d_out;

    cudaFuncSetAttribute(lstm_main, cudaFuncAttributeMaxDynamicSharedMemorySize, SMEM_TOT);

    pack_kernel<<<1544, 256>>>(W1,b1i,b1h,W2,b2i,b2h,W3,b3i,b3h);
    transpose_kernel<<<B_, 256>>>(x);
    lstm_main<<<NTILE, 128, SMEM_TOT>>>(f1w, f1b);
    fc2_kernel<<<M_/256, 256>>>(f2w, f2b, out);
}

// round 12
// speedup vs baseline: 1.0987x; 1.0987x over previous
#include <cuda_runtime.h>
#include <cuda_bf16.h>
#include <cstdint>
#include <cstddef>

#define B_ 8192
#define T_ 21
#define M_ (B_*T_)          /* 172032 = 1344*128 */
#define NTILE 1344
#define NSTAGES 64          /* 16 (L1) + 32 (L2) + 16 (L3) weight stages of 12KB */

/* smem byte offsets */
#define SO_A0    0u         /* 64KB: x (L1 in), then h2 (L3 in) */
#define SO_A1    65536u     /* 64KB: h1 (L2 in) */
#define SO_W     131072u    /* 4 x 12KB weight stage ring */
#define SO_BIAS  180224u    /* 1920 floats */
#define SO_FCW   187904u    /* 128 floats */
#define SO_RED   188416u    /* 128 floats */
#define SMEM_TOT 188928

/* ---- device scratch (allocation-free rule: __device__ globals) ---- */
__device__ __align__(128) unsigned char g_xA[(size_t)NTILE*32768];   /* per-tile swizzled bf16 x images */
__device__ __align__(128) unsigned char g_Wimg[NSTAGES*12288];       /* pre-swizzled weight stages */
__device__ float g_bias[1920];   /* [L1 i|g|o 768, L2 768, L3 384] */
__device__ float g_y[M_];

/* ---- helpers ---- */
__device__ __forceinline__ uint32_t s2u(const void* p){ return (uint32_t)__cvta_generic_to_shared(p); }
__device__ __forceinline__ void cpa16(void* dst, const void* src){
    asm volatile("cp.async.ca.shared.global [%0], [%1], 16;" :: "r"(s2u(dst)), "l"(src));
}
__device__ __forceinline__ void cp_commit(){ asm volatile("cp.async.commit_group;"); }
template<int N> __device__ __forceinline__ void cp_wait(){ asm volatile("cp.async.wait_group %0;" :: "n"(N)); }

__device__ __forceinline__ void ldsm4(uint32_t* r, const void* p){
    asm volatile("ldmatrix.sync.aligned.m8n8.x4.shared.b16 {%0,%1,%2,%3}, [%4];"
        : "=r"(r[0]),"=r"(r[1]),"=r"(r[2]),"=r"(r[3]) : "r"(s2u(p)));
}
__device__ __forceinline__ void mma16816(float* c, const uint32_t* a, uint32_t b0, uint32_t b1){
    asm volatile("mma.sync.aligned.m16n8k16.row.col.f32.bf16.bf16.f32 "
        "{%0,%1,%2,%3},{%4,%5,%6,%7},{%8,%9},{%0,%1,%2,%3};"
        : "+f"(c[0]),"+f"(c[1]),"+f"(c[2]),"+f"(c[3])
        : "r"(a[0]),"r"(a[1]),"r"(a[2]),"r"(a[3]),"r"(b0),"r"(b1));
}
__device__ __forceinline__ uint32_t pk2(float lo, float hi){
    uint32_t r; asm("cvt.rn.bf16x2.f32 %0, %1, %2;" : "=r"(r) : "f"(hi), "f"(lo)); return r;
}
/* fast activations: 4 MUFU per hval */
__device__ __forceinline__ float tanhap(float x){
    float y; asm("tanh.approx.f32 %0, %1;" : "=f"(y) : "f"(x)); return y;
}
__device__ __forceinline__ float sigap(float x){ return fmaf(tanhap(0.5f*x), 0.5f, 0.5f); }
__device__ __forceinline__ float hval(float iv, float gv, float ov){
    float cv = sigap(iv) * tanhap(gv);
    return sigap(ov) * tanhap(cv);
}

/* ---- prep: weights -> pre-swizzled 12KB stages in consumption order ---- */
__global__ void pack_kernel(const float* __restrict__ W1,const float* __restrict__ b1i,const float* __restrict__ b1h,
                            const float* __restrict__ W2,const float* __restrict__ b2i,const float* __restrict__ b2h,
                            const float* __restrict__ W3,const float* __restrict__ b3i,const float* __restrict__ b3h){
    int idx = blockIdx.x*256 + threadIdx.x;
    if (idx < NSTAGES*6144){
        int ss = idx / 6144, e = idx % 6144;
        int nrow = e >> 6, kk = e & 63;
        int l, jc, kc;
        if (ss < 16){ l = 0; jc = ss >> 1; kc = ss & 1; }
        else if (ss < 48){ int s = ss-16; l = 1; jc = s >> 2; kc = s & 3; }
        else { int s = ss-48; l = 2; jc = s >> 2; kc = s & 3; }
        int g = nrow >> 5, n = nrow & 31;
        int H = (l<2) ? 256 : 128;
        int K = (l==0) ? 128 : 256;
        int j = jc*32 + n;
        int row = (g==0) ? j : (g==1) ? 2*H+j : 3*H+j;   /* gates i,g,o from i,f,g,o */
        const float* W = (l==0) ? W1 : (l==1) ? W2 : W3;
        float v = W[(size_t)row*K + kc*64 + kk];
        uint32_t off = (uint32_t)nrow*128u + ((((uint32_t)(kk>>3)) ^ (nrow&7))<<4) + ((2u*kk)&15);
        *reinterpret_cast<__nv_bfloat16*>(g_Wimg + (size_t)ss*12288 + off) = __float2bfloat16_rn(v);
        return;
    }
    idx -= NSTAGES*6144;
    if (idx < 1920){
        int l = (idx<768)?0:(idx<1536)?1:2;
        int base = (l==0)?0:(l==1)?768:1536;
        int H = (l<2)?256:128;
        int q = idx - base, g = q / H, j = q % H;
        int row = (g==0)? j : (g==1)? 2*H+j : 3*H+j;
        const float* bi = (l==0)?b1i:(l==1)?b2i:b3i;
        const float* bh = (l==0)?b1h:(l==1)?b2h:b3h;
        g_bias[idx] = bi[row] + bh[row];
    }
}

/* ---- prep: x (B,128,21) -> per-tile swizzled bf16 A images (row 256B) ---- */
__global__ void transpose_kernel(const float* __restrict__ x){
    __shared__ float sx[2688];
    int b = blockIdx.x, tid = threadIdx.x;   /* 256 threads */
    const float* xb = x + (size_t)b*2688;
    for (int i = tid; i < 2688; i += 256) sx[i] = xb[i];
    __syncthreads();
    for (int i = tid; i < 1344; i += 256){
        int t = i >> 6, kp = (i & 63) * 2;
        int m = b*21 + t, tt = m >> 7, r = m & 127;
        uint32_t v = pk2(sx[kp*21 + t], sx[(kp+1)*21 + t]);
        uint32_t off = (uint32_t)r*256u + ((((uint32_t)(kp>>3)) ^ (r&7))<<4) + ((2u*kp)&15);
        *reinterpret_cast<uint32_t*>(g_xA + (size_t)tt*32768 + off) = v;
    }
}

/* ---- weight stage fill: pure linear copy (image pre-swizzled) ---- */
__device__ __forceinline__ void fill_stage(char* smem, int s, int tid){
    char* dst = smem + SO_W + (uint32_t)(s&3)*12288u;
    const unsigned char* src = g_Wimg + (size_t)s*12288;
    #pragma unroll
    for (int it = 0; it < 3; ++it){
        int ch = tid + it*256;
        cpa16(dst + ch*16, src + ch*16);
    }
}

/* ---- epilogue for one h-pair q (0..7) of column-chunk pjc ---- */
template<int H, int LAST>
__device__ __forceinline__ void epi_pair(float (&accP)[3][2][2][4], int q, int pjc,
                                         char* Aout, const float* fcw, float* yp,
                                         int lane, int mw, int nw){
    const int nf = q >> 2, mf = (q >> 1) & 1, hf = q & 1;
    const int j0 = pjc*32 + nw*16 + nf*8 + 2*(lane & 3);
    const float h0 = hval(accP[0][mf][nf][2*hf],   accP[1][mf][nf][2*hf],   accP[2][mf][nf][2*hf]);
    const float h1 = hval(accP[0][mf][nf][2*hf+1], accP[1][mf][nf][2*hf+1], accP[2][mf][nf][2*hf+1]);
    if (!LAST){
        const uint32_t row = 32*mw + 16*mf + 8*hf + (lane>>2);
        const uint32_t b = 2u*(uint32_t)j0;
        const uint32_t off = row*(2u*H) + ((((b>>4) ^ (row&7)))<<4) + (b&15);
        *reinterpret_cast<uint32_t*>(Aout + off) = pk2(h0, h1);
    } else {
        yp[mf*2+hf] = fmaf(h0, fcw[j0], fmaf(h1, fcw[j0+1], yp[mf*2+hf]));
    }
}

/* ---- one jc pass: accumulate column-chunk jc; if DEF, drain accP interleaved per-ks ---- */
template<int K, int H, int LAST, int DEF>
__device__ __forceinline__ void kc_pass(char* smem, const char* Ain, char* Aout,
                                        float (&acc)[3][2][2][4], float (&accP)[3][2][2][4],
                                        int jc, int pjc, int& ss,
                                        const float* biasL, const float* fcw, float* yp, int tid){
    const int wid = tid >> 5, lane = tid & 31;
    const int mw = wid >> 1, nw = wid & 1;
    const uint32_t arow = 32*mw + (lane & 15);
    const uint32_t ax = arow & 7;
    const uint32_t nrow = nw*16 + 8*(lane>>4) + (lane & 7);
    const uint32_t bx = nrow & 7;
    constexpr int NK = K/64;
    constexpr int CH = 8/NK;       /* h-pairs drained per kc */

    /* bias-folded accumulator init */
    {
        const int j0b = jc*32 + nw*16 + 2*(lane & 3);
        #pragma unroll
        for (int g = 0; g < 3; ++g){
            #pragma unroll
            for (int nf = 0; nf < 2; ++nf){
                const float b0v = biasL[g*H + j0b + nf*8];
                const float b1v = biasL[g*H + j0b + nf*8 + 1];
                #pragma unroll
                for (int mf = 0; mf < 2; ++mf){
                    #pragma unroll
                    for (int hf = 0; hf < 2; ++hf){
                        acc[g][mf][nf][2*hf]   = b0v;
                        acc[g][mf][nf][2*hf+1] = b1v;
                    }
                }
            }
        }
    }

    #pragma unroll
    for (int kc = 0; kc < NK; ++kc){
        cp_wait<2>();
        __syncthreads();               /* stage ss visible to all */
        const char* ws = smem + SO_W + (uint32_t)(ss&3)*12288u;
        #pragma unroll
        for (int ks = 0; ks < 4; ++ks){
            const uint32_t cA = (uint32_t)(kc*8 + 2*ks) + (lane>>4);
            const uint32_t aoff = arow*(2u*K) + (((cA ^ ax))<<4);
            uint32_t a0[4], a1[4];
            ldsm4(a0, Ain + aoff);
            ldsm4(a1, Ain + aoff + 32u*K);
            const uint32_t cb = (uint32_t)(2*ks) + ((lane>>3)&1);
            const uint32_t boff = nrow*128u + (((cb ^ bx))<<4);
            uint32_t b0[4], b1[4], b2[4];
            ldsm4(b0, ws + boff);
            ldsm4(b1, ws + boff + 4096);
            ldsm4(b2, ws + boff + 8192);
            mma16816(acc[0][0][0], a0, b0[0], b0[1]);
            mma16816(acc[0][0][1], a0, b0[2], b0[3]);
            mma16816(acc[0][1][0], a1, b0[0], b0[1]);
            mma16816(acc[0][1][1], a1, b0[2], b0[3]);
            mma16816(acc[1][0][0], a0, b1[0], b1[1]);
            mma16816(acc[1][0][1], a0, b1[2], b1[3]);
            mma16816(acc[1][1][0], a1, b1[0], b1[1]);
            mma16816(acc[1][1][1], a1, b1[2], b1[3]);
            mma16816(acc[2][0][0], a0, b2[0], b2[1]);
            mma16816(acc[2][0][1], a0, b2[2], b2[3]);
            mma16816(acc[2][1][0], a1, b2[0], b2[1]);
            mma16816(acc[2][1][1], a1, b2[2], b2[3]);
            /* interleaved drain: MUFU chain issues while the 12 HMMAs above
               occupy the tensor pipe — one h-pair per ks (K=128) or per 2 ks (K=256) */
            if (DEF){
                if (CH == 4){
                    epi_pair<H,LAST>(accP, kc*4 + ks, pjc, Aout, fcw, yp, lane, mw, nw);
                } else if ((ks & 1) == 1){
                    epi_pair<H,LAST>(accP, kc*2 + (ks>>1), pjc, Aout, fcw, yp, lane, mw, nw);
                }
            }
        }
        if (ss + 3 < NSTAGES) fill_stage(smem, ss + 3, tid);
        cp_commit();                   /* exactly one commit per kc */
        ++ss;
    }
}

/* ---- one fused layer with cross-jc software pipelining ---- */
template<int K, int H, int LAST>
__device__ __forceinline__ void run_layer(char* smem, const char* Ain, char* Aout,
                                          int& ss, const float* biasL, const float* fcw,
                                          float* yp, int tid){
    constexpr int NJ = H/32;           /* even: 8 or 4 */
    const int wid = tid >> 5, lane = tid & 31;
    const int mw = wid >> 1, nw = wid & 1;
    float accA[3][2][2][4], accB[3][2][2][4];

    kc_pass<K,H,LAST,0>(smem, Ain, Aout, accA, accB, 0, 0, ss, biasL, fcw, yp, tid);
    #pragma unroll 1
    for (int jcp = 0; jcp + 1 < NJ; jcp += 2){
        kc_pass<K,H,LAST,1>(smem, Ain, Aout, accB, accA, jcp+1, jcp,   ss, biasL, fcw, yp, tid);
        if (jcp + 2 < NJ)
            kc_pass<K,H,LAST,1>(smem, Ain, Aout, accA, accB, jcp+2, jcp+1, ss, biasL, fcw, yp, tid);
    }
    /* final serial drain: jc = NJ-1 lives in accB (NJ even) */
    #pragma unroll
    for (int q = 0; q < 8; ++q)
        epi_pair<H,LAST>(accB, q, NJ-1, Aout, fcw, yp, lane, mw, nw);
}

/* ---- fused main kernel: 3 LSTM layers + fc1 ---- */
__global__ void __launch_bounds__(256,1)
lstm_main(const float* __restrict__ fc1w, const float* __restrict__ fc1b){
    extern __shared__ char smem[];
    char* A0 = smem + SO_A0;
    char* A1 = smem + SO_A1;
    float* biasS = (float*)(smem + SO_BIAS);
    float* fcw   = (float*)(smem + SO_FCW);
    float* red   = (float*)(smem + SO_RED);
    const int tid = threadIdx.x, lane = tid & 31, wid = tid >> 5;
    const int mw = wid >> 1, nw = wid & 1;
    const float fc1b0 = __ldg(fc1b);

    /* x tile -> A0 */
    #pragma unroll
    for (int it = 0; it < 8; ++it){
        int ch = tid + it*256;
        cpa16(A0 + ch*16, g_xA + (size_t)blockIdx.x*32768 + ch*16);
    }
    cp_commit();
    fill_stage(smem, 0, tid); cp_commit();
    fill_stage(smem, 1, tid); cp_commit();
    fill_stage(smem, 2, tid); cp_commit();

    for (int i = tid; i < 1920; i += 256) biasS[i] = g_bias[i];
    if (tid < 128) fcw[tid] = fc1w[tid];

    int ss = 0;
    float yp[4] = {0.f, 0.f, 0.f, 0.f};
    run_layer<128,256,0>(smem, A0, A1, ss, biasS,        fcw, yp, tid);
    run_layer<256,256,0>(smem, A1, A0, ss, biasS + 768,  fcw, yp, tid);
    run_layer<256,128,1>(smem, A0, A1, ss, biasS + 1536, fcw, yp, tid);

    /* fc1 reduce: sum across quad lanes, then across nw halves */
    #pragma unroll
    for (int k = 0; k < 4; ++k){
        yp[k] += __shfl_xor_sync(0xffffffffu, yp[k], 1);
        yp[k] += __shfl_xor_sync(0xffffffffu, yp[k], 2);
    }
    __syncthreads();
    if (nw == 0 && (lane & 3) == 0){
        #pragma unroll
        for (int k = 0; k < 4; ++k){
            int row = 32*mw + 16*(k>>1) + 8*(k&1) + (lane>>2);
            red[row] = yp[k];
        }
    }
    __syncthreads();
    if (nw == 1 && (lane & 3) == 0){
        #pragma unroll
        for (int k = 0; k < 4; ++k){
            int row = 32*mw + 16*(k>>1) + 8*(k&1) + (lane>>2);
            g_y[(size_t)blockIdx.x*128 + row] = red[row] + yp[k] + fc1b0;
        }
    }
}

/* ---- fc2: out[b,0,t] = sum_j y[b,j]*w[t,j] + bias[t] ---- */
__global__ void fc2_kernel(const float* __restrict__ w, const float* __restrict__ bias,
                           float* __restrict__ out){
    __shared__ float sw[T_*T_];
    __shared__ float sbv[T_];
    int tid = threadIdx.x;
    for (int i = tid; i < T_*T_; i += 256) sw[i] = w[i];
    if (tid < T_) sbv[tid] = bias[tid];
    __syncthreads();
    int gidx = blockIdx.x*256 + tid;
    int b = gidx / T_, t = gidx - b*T_;
    const float* yb = g_y + (size_t)b*T_;
    float s = sbv[t];
    #pragma unroll
    for (int j = 0; j < T_; ++j) s += yb[j]*sw[t*T_ + j];
    out[gidx] = s;
}

/* ---- launch ---- */
extern "C" void kernel_launch(void* const* d_in, const int* in_sizes, int n_in,
                              void* d_out, int out_size){
    const float* x   = (const float*)d_in[0];
    const float* W1  = (const float*)d_in[1];
    const float* b1i = (const float*)d_in[2];
    const float* b1h = (const float*)d_in[3];
    const float* W2  = (const float*)d_in[4];
    const float* b2i = (const float*)d_in[5];
    const float* b2h = (const float*)d_in[6];
    const float* W3  = (const float*)d_in[7];
    const float* b3i = (const float*)d_in[8];
    const float* b3h = (const float*)d_in[9];
    const float* f1w = (const float*)d_in[10];
    const float* f1b = (const float*)d_in[11];
    const float* f2w = (const float*)d_in[12];
    const float* f2b = (const float*)d_in[13];
    float* out = (float*)d_out;

    cudaFuncSetAttribute(lstm_main, cudaFuncAttributeMaxDynamicSharedMemorySize, SMEM_TOT);

    pack_kernel<<<1544, 256>>>(W1,b1i,b1h,W2,b2i,b2h,W3,b3i,b3h);
    transpose_kernel<<<B_, 256>>>(x);
    lstm_main<<<NTILE, 256, SMEM_TOT>>>(f1w, f1b);
    fc2_kernel<<<M_/256, 256>>>(f2w, f2b, out);
}